// round 10
// baseline (speedup 1.0000x reference)
#include <cuda_runtime.h>

#define HID      64
#define NCLASS   100
#define MAXN     100000
#define MAXE     1600000
#define NGRAPH_MAX 512
#define ID_OFFSET 1500
#define BN_EPS   1e-5f
#define MLP_BLOCK 96   // 3 warps, 96 nodes per block

// Scratch (no cudaMalloc allowed)
__device__ float4 g_h4[MAXN * 16];              // [N][64] as float4[N][16]
__device__ float4 g_x4[MAXN * 16];
__device__ float4 g_pooled4[NGRAPH_MAX * 48];   // [G][192] as float4[G][48]
__device__ float  g_stats[3 * 128];             // per layer: 64 sums, 64 sumsq
// CSR (built once per call; edges constant across layers)
__device__ int    g_off[MAXN + 1];
__device__ int    g_cur[MAXN];
__device__ int    g_adj[MAXE];

__device__ __forceinline__ void red_add_v4(float4* addr, float4 v) {
    asm volatile("red.global.add.v4.f32 [%0], {%1, %2, %3, %4};"
                 :: "l"(addr), "f"(v.x), "f"(v.y), "f"(v.z), "f"(v.w)
                 : "memory");
}

// ---- packed f32x2 helpers (Blackwell sm_103a) --------------------------------
__device__ __forceinline__ unsigned long long pack2(float a, float b) {
    unsigned long long r;
    asm("mov.b64 %0, {%1, %2};" : "=l"(r) : "f"(a), "f"(b));
    return r;
}
__device__ __forceinline__ void fma2(unsigned long long& d,
                                     unsigned long long a, unsigned long long b) {
    asm("fma.rn.f32x2 %0, %1, %2, %0;" : "+l"(d) : "l"(a), "l"(b));
}
__device__ __forceinline__ void unpack2(unsigned long long v, float& a, float& b) {
    asm("mov.b64 {%0, %1}, %2;" : "=f"(a), "=f"(b) : "l"(v));
}

// ---------------------------------------------------------------- zero scratch
__global__ void zero_kernel(int N) {
    int i = blockIdx.x * blockDim.x + threadIdx.x;
    if (i < NGRAPH_MAX * 48) g_pooled4[i] = make_float4(0.f, 0.f, 0.f, 0.f);
    if (i < 3 * 128)         g_stats[i] = 0.f;
    if (i < N)               g_cur[i] = 0;
}

// ------------------------------------------------------- CSR build: histogram
__global__ void hist_kernel(const int* __restrict__ dst, int E) {
    int e = blockIdx.x * blockDim.x + threadIdx.x;
    if (e < E) atomicAdd(&g_cur[__ldg(&dst[e])], 1);
}

// ---------------------------------- CSR build: 1-block exclusive scan of g_cur
__global__ void scan_kernel(int N, int E) {
    __shared__ int part[1024];
    int t = threadIdx.x;
    int chunk = (N + 1023) >> 10;
    int lo = t * chunk, hi = min(lo + chunk, N);
    int s = 0;
    for (int i = lo; i < hi; i++) s += g_cur[i];
    part[t] = s;
    __syncthreads();
    for (int d = 1; d < 1024; d <<= 1) {
        int v = (t >= d) ? part[t - d] : 0;
        __syncthreads();
        part[t] += v;
        __syncthreads();
    }
    int run = (t == 0) ? 0 : part[t - 1];
    for (int i = lo; i < hi; i++) {
        int cnt = g_cur[i];
        g_off[i] = run;
        g_cur[i] = run;        // cursor for fill phase
        run += cnt;
    }
    if (t == 1023) g_off[N] = E;
}

// ---------------------------------------------------------- CSR build: fill
__global__ void fill_kernel(const int* __restrict__ src,
                            const int* __restrict__ dst, int E) {
    int e = blockIdx.x * blockDim.x + threadIdx.x;
    if (e < E) {
        int d = __ldg(&dst[e]);
        int pos = atomicAdd(&g_cur[d], 1);
        g_adj[pos] = __ldg(&src[e]);
    }
}

// ------------------------------------------------------ h = emb[ids+1500]
__global__ void gather_kernel(const int* __restrict__ node_ids,
                              const float4* __restrict__ emb4, int N) {
    int i = blockIdx.x * blockDim.x + threadIdx.x;
    if (i >= N * 16) return;
    int node = i >> 4, c = i & 15;
    int id = __ldg(&node_ids[node]) + ID_OFFSET;
    g_h4[i] = __ldg(&emb4[id * 16 + c]);
}

// -------------- pull-mode aggregation: x[n] = (1+eps_l)*h[n] + sum h[adj(n)]
__global__ void aggregate_kernel(const float* __restrict__ eps, int l, int N) {
    int i = blockIdx.x * blockDim.x + threadIdx.x;
    if (i >= N * 16) return;
    int n = i >> 4, c = i & 15;
    const float4* __restrict__ h4 = (const float4*)g_h4;
    const int* __restrict__ adj = g_adj;

    float s = 1.f + __ldg(&eps[l]);
    float4 h = h4[i];
    float4 acc = make_float4(h.x * s, h.y * s, h.z * s, h.w * s);

    int e = g_off[n], end = g_off[n + 1];
    // 4-deep pipeline: batch independent index + feature loads (MLP=4)
    for (; e + 4 <= end; e += 4) {
        int s0 = __ldg(&adj[e]);
        int s1 = __ldg(&adj[e + 1]);
        int s2 = __ldg(&adj[e + 2]);
        int s3 = __ldg(&adj[e + 3]);
        float4 v0 = h4[s0 * 16 + c];
        float4 v1 = h4[s1 * 16 + c];
        float4 v2 = h4[s2 * 16 + c];
        float4 v3 = h4[s3 * 16 + c];
        acc.x += (v0.x + v1.x) + (v2.x + v3.x);
        acc.y += (v0.y + v1.y) + (v2.y + v3.y);
        acc.z += (v0.z + v1.z) + (v2.z + v3.z);
        acc.w += (v0.w + v1.w) + (v2.w + v3.w);
    }
    for (; e < end; e++) {
        int s0 = __ldg(&adj[e]);
        float4 v = h4[s0 * 16 + c];
        acc.x += v.x; acc.y += v.y; acc.z += v.z; acc.w += v.w;
    }
    g_x4[i] = acc;
}

// --------------------------- x = relu(relu(relu(x W0 + b0) W1 + b1) W2 + b2)
__global__ void __launch_bounds__(MLP_BLOCK) mlp_kernel(const float4* __restrict__ Ws4,
                                                        const float* __restrict__ bs,
                                                        int l, int N) {
    __shared__ float  sx[MLP_BLOCK * 65];   // 96 x 64 node features, stride 65
    __shared__ float4 sW4[1024];            // one 64x64 W, swizzled
    __shared__ float4 sb4[16];

    int tid  = threadIdx.x;
    int warp = tid >> 5, lane = tid & 31;
    int ng = lane & 7, jc = lane >> 3;
    int nodeBase = blockIdx.x * MLP_BLOCK;
    int nl0 = warp * 32 + ng * 4;           // this lane's first local node

    #pragma unroll
    for (int r = 0; r < 16; r++) {
        int node_l = r * 6 + (tid >> 4);
        int c = tid & 15;
        int node = nodeBase + node_l;
        float4 v = (node < N) ? g_x4[node * 16 + c] : make_float4(0.f,0.f,0.f,0.f);
        int b = node_l * 65 + c * 4;
        sx[b] = v.x; sx[b+1] = v.y; sx[b+2] = v.z; sx[b+3] = v.w;
    }

    const ulonglong2* sW2 = (const ulonglong2*)sW4;

    for (int m = 0; m < 3; m++) {
        __syncthreads();
        const float4* W4 = Ws4 + (l * 3 + m) * 1024;
        for (int t = tid; t < 1024; t += MLP_BLOCK) {
            int k = t >> 4, c = t & 15;
            int jj = c >> 2, q = c & 3;
            sW4[k * 16 + jj * 4 + ((q + jj) & 3)] = __ldg(&W4[t]);
        }
        if (tid < 16) {
            const float4* b4 = (const float4*)(bs + (l * 3 + m) * 64);
            sb4[tid] = __ldg(&b4[tid]);
        }
        __syncthreads();

        const unsigned long long* sbU = (const unsigned long long*)sb4;
        unsigned long long acc[4][8];   // [node i][output pair p] of chunk jc
        #pragma unroll
        for (int p = 0; p < 8; p++) {
            unsigned long long bv = sbU[jc * 8 + p];
            acc[0][p] = bv; acc[1][p] = bv; acc[2][p] = bv; acc[3][p] = bv;
        }

        #pragma unroll 4
        for (int k = 0; k < 64; k++) {
            unsigned long long xp[4];
            #pragma unroll
            for (int i = 0; i < 4; i++) {
                float xv = sx[(nl0 + i) * 65 + k];
                xp[i] = pack2(xv, xv);
            }
            #pragma unroll
            for (int q = 0; q < 4; q++) {
                ulonglong2 w = sW2[k * 16 + jc * 4 + ((q + jc) & 3)];
                #pragma unroll
                for (int i = 0; i < 4; i++) {
                    fma2(acc[i][2*q],   xp[i], w.x);
                    fma2(acc[i][2*q+1], xp[i], w.y);
                }
            }
        }

        if (m < 2) {
            __syncwarp();   // sx rows are warp-private: readers done before rewrite
            #pragma unroll
            for (int i = 0; i < 4; i++) {
                #pragma unroll
                for (int p = 0; p < 8; p++) {
                    float a, b; unpack2(acc[i][p], a, b);
                    int base = (nl0 + i) * 65 + jc * 16 + 2 * p;
                    sx[base]     = fmaxf(a, 0.f);
                    sx[base + 1] = fmaxf(b, 0.f);
                }
            }
        } else {
            #pragma unroll
            for (int i = 0; i < 4; i++) {
                int node = nodeBase + nl0 + i;
                if (node < N) {
                    #pragma unroll
                    for (int q = 0; q < 4; q++) {
                        float a, b, c2, d;
                        unpack2(acc[i][2*q],   a, b);
                        unpack2(acc[i][2*q+1], c2, d);
                        g_x4[node * 16 + jc * 4 + q] =
                            make_float4(fmaxf(a,0.f), fmaxf(b,0.f),
                                        fmaxf(c2,0.f), fmaxf(d,0.f));
                    }
                }
            }
        }
    }
}

// -------------------------------------- per-feature sum / sumsq over x (for BN)
__global__ void stats_kernel(int l, int N) {
    __shared__ float4 ssum[256];
    __shared__ float4 ssq[256];
    int tid = threadIdx.x;
    int f4 = tid & 15;
    int r  = tid >> 4;
    float4 s = make_float4(0.f, 0.f, 0.f, 0.f);
    float4 q = make_float4(0.f, 0.f, 0.f, 0.f);
    for (int row = blockIdx.x * 16 + r; row < N; row += gridDim.x * 16) {
        float4 v = g_x4[row * 16 + f4];
        s.x += v.x; s.y += v.y; s.z += v.z; s.w += v.w;
        q.x += v.x * v.x; q.y += v.y * v.y; q.z += v.z * v.z; q.w += v.w * v.w;
    }
    ssum[tid] = s; ssq[tid] = q;
    __syncthreads();
    for (int half = 8; half >= 1; half >>= 1) {
        if (r < half) {
            float4 a = ssum[tid + half * 16];
            float4 b = ssq [tid + half * 16];
            float4 cs = ssum[tid], cq = ssq[tid];
            cs.x += a.x; cs.y += a.y; cs.z += a.z; cs.w += a.w;
            cq.x += b.x; cq.y += b.y; cq.z += b.z; cq.w += b.w;
            ssum[tid] = cs; ssq[tid] = cq;
        }
        __syncthreads();
    }
    if (r == 0) {
        float4 cs = ssum[tid], cq = ssq[tid];
        atomicAdd(&g_stats[l*128 + f4*4 + 0], cs.x);
        atomicAdd(&g_stats[l*128 + f4*4 + 1], cs.y);
        atomicAdd(&g_stats[l*128 + f4*4 + 2], cs.z);
        atomicAdd(&g_stats[l*128 + f4*4 + 3], cs.w);
        atomicAdd(&g_stats[l*128 + 64 + f4*4 + 0], cq.x);
        atomicAdd(&g_stats[l*128 + 64 + f4*4 + 1], cq.y);
        atomicAdd(&g_stats[l*128 + 64 + f4*4 + 2], cq.z);
        atomicAdd(&g_stats[l*128 + 64 + f4*4 + 3], cq.w);
    }
}

// ---------------------- h = BN(x); pooled[g] += h  (next-layer init now in agg)
__global__ void finalize_kernel(const int* __restrict__ graph_ids,
                                const float* __restrict__ gamma,
                                const float* __restrict__ beta,
                                int l, int N) {
    int i = blockIdx.x * blockDim.x + threadIdx.x;
    if (i >= N * 16) return;
    int node = i >> 4, c = i & 15;
    float invN = 1.f / (float)N;
    float sc[4], sh[4];
    #pragma unroll
    for (int j = 0; j < 4; j++) {
        int f = c * 4 + j;
        float su = g_stats[l*128 + f];
        float sq = g_stats[l*128 + 64 + f];
        float mean = su * invN;
        float var  = sq * invN - mean * mean;
        float gm = __ldg(&gamma[l*64 + f]);
        float bt = __ldg(&beta [l*64 + f]);
        float s = gm * rsqrtf(var + BN_EPS);
        sc[j] = s;
        sh[j] = bt - mean * s;
    }
    float4 v = g_x4[i];
    float4 h;
    h.x = v.x * sc[0] + sh[0];
    h.y = v.y * sc[1] + sh[1];
    h.z = v.z * sc[2] + sh[2];
    h.w = v.w * sc[3] + sh[3];
    g_h4[i] = h;
    int g = __ldg(&graph_ids[node]);
    red_add_v4(&g_pooled4[g * 48 + l * 16 + c], h);
}

// ----------------------------------------- out[g] = pooled[g] @ W_out + b_out
__global__ void out_kernel(const float* __restrict__ W_out,
                           const float* __restrict__ b_out,
                           float* __restrict__ out, int G) {
    __shared__ float sp[192];
    int g = blockIdx.x;
    const float* prow = (const float*)g_pooled4 + g * 192;
    if (threadIdx.x < 192) sp[threadIdx.x] = prow[threadIdx.x];
    __syncthreads();
    int c = threadIdx.x;
    if (c < NCLASS) {
        float acc = __ldg(&b_out[c]);
        #pragma unroll 8
        for (int k = 0; k < 192; k++)
            acc = fmaf(sp[k], __ldg(&W_out[k * NCLASS + c]), acc);
        out[g * NCLASS + c] = acc;
    }
}

extern "C" void kernel_launch(void* const* d_in, const int* in_sizes, int n_in,
                              void* d_out, int out_size) {
    const int*   node_ids  = (const int*)  d_in[0];
    const int*   edge_src  = (const int*)  d_in[1];
    const int*   edge_dst  = (const int*)  d_in[2];
    const int*   graph_ids = (const int*)  d_in[3];
    const float* emb       = (const float*)d_in[4];
    const float* Ws        = (const float*)d_in[5];
    const float* bs        = (const float*)d_in[6];
    const float* bn_gamma  = (const float*)d_in[7];
    const float* bn_beta   = (const float*)d_in[8];
    const float* eps       = (const float*)d_in[9];
    const float* W_out     = (const float*)d_in[10];
    const float* b_out     = (const float*)d_in[11];
    float* out = (float*)d_out;

    int N = in_sizes[0];
    int E = in_sizes[1];
    int G = out_size / NCLASS;

    int gN  = (N * 16 + 255) / 256;
    int gE1 = (E + 255) / 256;
    int gZ  = (N + 255) / 256;

    zero_kernel<<<gZ, 256>>>(N);
    hist_kernel<<<gE1, 256>>>(edge_dst, E);
    gather_kernel<<<gN, 256>>>(node_ids, (const float4*)emb, N);
    scan_kernel<<<1, 1024>>>(N, E);
    fill_kernel<<<gE1, 256>>>(edge_src, edge_dst, E);
    for (int l = 0; l < 3; l++) {
        aggregate_kernel<<<gN, 256>>>(eps, l, N);
        mlp_kernel<<<(N + MLP_BLOCK - 1) / MLP_BLOCK, MLP_BLOCK>>>((const float4*)Ws, bs, l, N);
        stats_kernel<<<512, 256>>>(l, N);
        finalize_kernel<<<gN, 256>>>(graph_ids, bn_gamma, bn_beta, l, N);
    }
    out_kernel<<<G, 192>>>(W_out, b_out, out, G);
}

// round 12
// speedup vs baseline: 1.2611x; 1.2611x over previous
#include <cuda_runtime.h>

#define HID      64
#define NCLASS   100
#define MAXN     100000
#define MAXE     1600000
#define NGRAPH_MAX 512
#define ID_OFFSET 1500
#define BN_EPS   1e-5f
#define MLP_BLOCK 96   // 3 warps, 96 nodes per block
#define SCAN_BS  1024
#define MAX_SCAN_BLOCKS 128

// Scratch (no cudaMalloc allowed)
__device__ float4 g_h4[MAXN * 16];              // [N][64] as float4[N][16]
__device__ float4 g_x4[MAXN * 16];
__device__ float4 g_pooled4[NGRAPH_MAX * 48];   // [G][192] as float4[G][48]
__device__ float  g_stats[3 * 128];             // per layer: 64 sums, 64 sumsq
// CSR (built once per call; edges constant across layers)
__device__ int    g_off[MAXN + 1];
__device__ int    g_cur[MAXN];
__device__ int    g_adj[MAXE];
__device__ int    g_blocksum[MAX_SCAN_BLOCKS];

__device__ __forceinline__ void red_add_v4(float4* addr, float4 v) {
    asm volatile("red.global.add.v4.f32 [%0], {%1, %2, %3, %4};"
                 :: "l"(addr), "f"(v.x), "f"(v.y), "f"(v.z), "f"(v.w)
                 : "memory");
}

// ---- packed f32x2 helpers (Blackwell sm_103a) --------------------------------
__device__ __forceinline__ unsigned long long pack2(float a, float b) {
    unsigned long long r;
    asm("mov.b64 %0, {%1, %2};" : "=l"(r) : "f"(a), "f"(b));
    return r;
}
__device__ __forceinline__ void fma2(unsigned long long& d,
                                     unsigned long long a, unsigned long long b) {
    asm("fma.rn.f32x2 %0, %1, %2, %0;" : "+l"(d) : "l"(a), "l"(b));
}
__device__ __forceinline__ void unpack2(unsigned long long v, float& a, float& b) {
    asm("mov.b64 {%0, %1}, %2;" : "=f"(a), "=f"(b) : "l"(v));
}

// ---------------------------------------------------------------- zero scratch
__global__ void zero_kernel(int N) {
    int i = blockIdx.x * blockDim.x + threadIdx.x;
    if (i < NGRAPH_MAX * 48) g_pooled4[i] = make_float4(0.f, 0.f, 0.f, 0.f);
    if (i < 3 * 128)         g_stats[i] = 0.f;
    if (i < N)               g_cur[i] = 0;
}

// ------------------------------------------------------- CSR build: histogram
__global__ void hist_kernel(const int* __restrict__ dst, int E) {
    int e = blockIdx.x * blockDim.x + threadIdx.x;
    if (e < E) atomicAdd(&g_cur[__ldg(&dst[e])], 1);
}

// -------------------- CSR build: device-wide exclusive scan, phase A (blocks)
__global__ void __launch_bounds__(SCAN_BS) scanA_kernel(int N) {
    __shared__ int warpsum[32];
    int i = blockIdx.x * SCAN_BS + threadIdx.x;
    int lane = threadIdx.x & 31, w = threadIdx.x >> 5;
    int v = (i < N) ? g_cur[i] : 0;
    int s = v;
    #pragma unroll
    for (int d = 1; d < 32; d <<= 1) {
        int t = __shfl_up_sync(0xffffffffu, s, d);
        if (lane >= d) s += t;
    }
    if (lane == 31) warpsum[w] = s;
    __syncthreads();
    if (w == 0) {
        int ws = warpsum[lane];
        #pragma unroll
        for (int d = 1; d < 32; d <<= 1) {
            int t = __shfl_up_sync(0xffffffffu, ws, d);
            if (lane >= d) ws += t;
        }
        warpsum[lane] = ws;
    }
    __syncthreads();
    int excl = s - v + (w > 0 ? warpsum[w - 1] : 0);
    if (i < N) g_off[i] = excl;            // block-local exclusive prefix
    if (threadIdx.x == SCAN_BS - 1) g_blocksum[blockIdx.x] = excl + v;
}

// ------------------- phase B: 1 small block scans the per-block totals
__global__ void scanB_kernel(int nb) {
    __shared__ int sh[MAX_SCAN_BLOCKS];
    int t = threadIdx.x;
    sh[t] = (t < nb) ? g_blocksum[t] : 0;
    __syncthreads();
    #pragma unroll
    for (int d = 1; d < MAX_SCAN_BLOCKS; d <<= 1) {
        int v = (t >= d) ? sh[t - d] : 0;
        __syncthreads();
        sh[t] += v;
        __syncthreads();
    }
    if (t < nb) g_blocksum[t] = (t == 0) ? 0 : sh[t - 1];   // exclusive
}

// ------------------- phase C: add block base, emit g_off / g_cur / g_off[N]
__global__ void __launch_bounds__(SCAN_BS) scanC_kernel(int N, int E) {
    int i = blockIdx.x * SCAN_BS + threadIdx.x;
    int base = g_blocksum[blockIdx.x];
    if (i < N) {
        int o = g_off[i] + base;
        g_off[i] = o;
        g_cur[i] = o;        // cursor for fill phase
    }
    if (i == 0) g_off[N] = E;
}

// ---------------------------------------------------------- CSR build: fill
__global__ void fill_kernel(const int* __restrict__ src,
                            const int* __restrict__ dst, int E) {
    int e = blockIdx.x * blockDim.x + threadIdx.x;
    if (e < E) {
        int d = __ldg(&dst[e]);
        int pos = atomicAdd(&g_cur[d], 1);
        g_adj[pos] = __ldg(&src[e]);
    }
}

// ------------------------------------------------------ h = emb[ids+1500]
__global__ void gather_kernel(const int* __restrict__ node_ids,
                              const float4* __restrict__ emb4, int N) {
    int i = blockIdx.x * blockDim.x + threadIdx.x;
    if (i >= N * 16) return;
    int node = i >> 4, c = i & 15;
    int id = __ldg(&node_ids[node]) + ID_OFFSET;
    g_h4[i] = __ldg(&emb4[id * 16 + c]);
}

// -------------- pull-mode aggregation: x[n] = (1+eps_l)*h[n] + sum h[adj(n)]
__global__ void aggregate_kernel(const float* __restrict__ eps, int l, int N) {
    int i = blockIdx.x * blockDim.x + threadIdx.x;
    if (i >= N * 16) return;
    int n = i >> 4, c = i & 15;
    const float4* __restrict__ h4 = (const float4*)g_h4;
    const int* __restrict__ adj = g_adj;

    float s = 1.f + __ldg(&eps[l]);
    float4 h = h4[i];
    float4 acc = make_float4(h.x * s, h.y * s, h.z * s, h.w * s);

    int e = g_off[n], end = g_off[n + 1];
    // 4-deep pipeline: batch independent index + feature loads (MLP=4)
    for (; e + 4 <= end; e += 4) {
        int s0 = __ldg(&adj[e]);
        int s1 = __ldg(&adj[e + 1]);
        int s2 = __ldg(&adj[e + 2]);
        int s3 = __ldg(&adj[e + 3]);
        float4 v0 = h4[s0 * 16 + c];
        float4 v1 = h4[s1 * 16 + c];
        float4 v2 = h4[s2 * 16 + c];
        float4 v3 = h4[s3 * 16 + c];
        acc.x += (v0.x + v1.x) + (v2.x + v3.x);
        acc.y += (v0.y + v1.y) + (v2.y + v3.y);
        acc.z += (v0.z + v1.z) + (v2.z + v3.z);
        acc.w += (v0.w + v1.w) + (v2.w + v3.w);
    }
    for (; e < end; e++) {
        int s0 = __ldg(&adj[e]);
        float4 v = h4[s0 * 16 + c];
        acc.x += v.x; acc.y += v.y; acc.z += v.z; acc.w += v.w;
    }
    g_x4[i] = acc;
}

// --------------------------- x = relu(relu(relu(x W0 + b0) W1 + b1) W2 + b2)
__global__ void __launch_bounds__(MLP_BLOCK) mlp_kernel(const float4* __restrict__ Ws4,
                                                        const float* __restrict__ bs,
                                                        int l, int N) {
    __shared__ float  sx[MLP_BLOCK * 65];   // 96 x 64 node features, stride 65
    __shared__ float4 sW4[1024];            // one 64x64 W, swizzled
    __shared__ float4 sb4[16];

    int tid  = threadIdx.x;
    int warp = tid >> 5, lane = tid & 31;
    int ng = lane & 7, jc = lane >> 3;
    int nodeBase = blockIdx.x * MLP_BLOCK;
    int nl0 = warp * 32 + ng * 4;           // this lane's first local node

    #pragma unroll
    for (int r = 0; r < 16; r++) {
        int node_l = r * 6 + (tid >> 4);
        int c = tid & 15;
        int node = nodeBase + node_l;
        float4 v = (node < N) ? g_x4[node * 16 + c] : make_float4(0.f,0.f,0.f,0.f);
        int b = node_l * 65 + c * 4;
        sx[b] = v.x; sx[b+1] = v.y; sx[b+2] = v.z; sx[b+3] = v.w;
    }

    const ulonglong2* sW2 = (const ulonglong2*)sW4;

    for (int m = 0; m < 3; m++) {
        __syncthreads();
        const float4* W4 = Ws4 + (l * 3 + m) * 1024;
        for (int t = tid; t < 1024; t += MLP_BLOCK) {
            int k = t >> 4, c = t & 15;
            int jj = c >> 2, q = c & 3;
            sW4[k * 16 + jj * 4 + ((q + jj) & 3)] = __ldg(&W4[t]);
        }
        if (tid < 16) {
            const float4* b4 = (const float4*)(bs + (l * 3 + m) * 64);
            sb4[tid] = __ldg(&b4[tid]);
        }
        __syncthreads();

        const unsigned long long* sbU = (const unsigned long long*)sb4;
        unsigned long long acc[4][8];   // [node i][output pair p] of chunk jc
        #pragma unroll
        for (int p = 0; p < 8; p++) {
            unsigned long long bv = sbU[jc * 8 + p];
            acc[0][p] = bv; acc[1][p] = bv; acc[2][p] = bv; acc[3][p] = bv;
        }

        #pragma unroll 4
        for (int k = 0; k < 64; k++) {
            unsigned long long xp[4];
            #pragma unroll
            for (int i = 0; i < 4; i++) {
                float xv = sx[(nl0 + i) * 65 + k];
                xp[i] = pack2(xv, xv);
            }
            #pragma unroll
            for (int q = 0; q < 4; q++) {
                ulonglong2 w = sW2[k * 16 + jc * 4 + ((q + jc) & 3)];
                #pragma unroll
                for (int i = 0; i < 4; i++) {
                    fma2(acc[i][2*q],   xp[i], w.x);
                    fma2(acc[i][2*q+1], xp[i], w.y);
                }
            }
        }

        if (m < 2) {
            __syncwarp();   // sx rows are warp-private: readers done before rewrite
            #pragma unroll
            for (int i = 0; i < 4; i++) {
                #pragma unroll
                for (int p = 0; p < 8; p++) {
                    float a, b; unpack2(acc[i][p], a, b);
                    int base = (nl0 + i) * 65 + jc * 16 + 2 * p;
                    sx[base]     = fmaxf(a, 0.f);
                    sx[base + 1] = fmaxf(b, 0.f);
                }
            }
        } else {
            #pragma unroll
            for (int i = 0; i < 4; i++) {
                int node = nodeBase + nl0 + i;
                if (node < N) {
                    #pragma unroll
                    for (int q = 0; q < 4; q++) {
                        float a, b, c2, d;
                        unpack2(acc[i][2*q],   a, b);
                        unpack2(acc[i][2*q+1], c2, d);
                        g_x4[node * 16 + jc * 4 + q] =
                            make_float4(fmaxf(a,0.f), fmaxf(b,0.f),
                                        fmaxf(c2,0.f), fmaxf(d,0.f));
                    }
                }
            }
        }
    }
}

// -------------------------------------- per-feature sum / sumsq over x (for BN)
__global__ void stats_kernel(int l, int N) {
    __shared__ float4 ssum[256];
    __shared__ float4 ssq[256];
    int tid = threadIdx.x;
    int f4 = tid & 15;
    int r  = tid >> 4;
    float4 s = make_float4(0.f, 0.f, 0.f, 0.f);
    float4 q = make_float4(0.f, 0.f, 0.f, 0.f);
    for (int row = blockIdx.x * 16 + r; row < N; row += gridDim.x * 16) {
        float4 v = g_x4[row * 16 + f4];
        s.x += v.x; s.y += v.y; s.z += v.z; s.w += v.w;
        q.x += v.x * v.x; q.y += v.y * v.y; q.z += v.z * v.z; q.w += v.w * v.w;
    }
    ssum[tid] = s; ssq[tid] = q;
    __syncthreads();
    for (int half = 8; half >= 1; half >>= 1) {
        if (r < half) {
            float4 a = ssum[tid + half * 16];
            float4 b = ssq [tid + half * 16];
            float4 cs = ssum[tid], cq = ssq[tid];
            cs.x += a.x; cs.y += a.y; cs.z += a.z; cs.w += a.w;
            cq.x += b.x; cq.y += b.y; cq.z += b.z; cq.w += b.w;
            ssum[tid] = cs; ssq[tid] = cq;
        }
        __syncthreads();
    }
    if (r == 0) {
        float4 cs = ssum[tid], cq = ssq[tid];
        atomicAdd(&g_stats[l*128 + f4*4 + 0], cs.x);
        atomicAdd(&g_stats[l*128 + f4*4 + 1], cs.y);
        atomicAdd(&g_stats[l*128 + f4*4 + 2], cs.z);
        atomicAdd(&g_stats[l*128 + f4*4 + 3], cs.w);
        atomicAdd(&g_stats[l*128 + 64 + f4*4 + 0], cq.x);
        atomicAdd(&g_stats[l*128 + 64 + f4*4 + 1], cq.y);
        atomicAdd(&g_stats[l*128 + 64 + f4*4 + 2], cq.z);
        atomicAdd(&g_stats[l*128 + 64 + f4*4 + 3], cq.w);
    }
}

// ---------------------- h = BN(x); pooled[g] += h  (next-layer init now in agg)
__global__ void finalize_kernel(const int* __restrict__ graph_ids,
                                const float* __restrict__ gamma,
                                const float* __restrict__ beta,
                                int l, int N) {
    int i = blockIdx.x * blockDim.x + threadIdx.x;
    if (i >= N * 16) return;
    int node = i >> 4, c = i & 15;
    float invN = 1.f / (float)N;
    float sc[4], sh[4];
    #pragma unroll
    for (int j = 0; j < 4; j++) {
        int f = c * 4 + j;
        float su = g_stats[l*128 + f];
        float sq = g_stats[l*128 + 64 + f];
        float mean = su * invN;
        float var  = sq * invN - mean * mean;
        float gm = __ldg(&gamma[l*64 + f]);
        float bt = __ldg(&beta [l*64 + f]);
        float s = gm * rsqrtf(var + BN_EPS);
        sc[j] = s;
        sh[j] = bt - mean * s;
    }
    float4 v = g_x4[i];
    float4 h;
    h.x = v.x * sc[0] + sh[0];
    h.y = v.y * sc[1] + sh[1];
    h.z = v.z * sc[2] + sh[2];
    h.w = v.w * sc[3] + sh[3];
    g_h4[i] = h;
    int g = __ldg(&graph_ids[node]);
    red_add_v4(&g_pooled4[g * 48 + l * 16 + c], h);
}

// ----------------------------------------- out[g] = pooled[g] @ W_out + b_out
__global__ void out_kernel(const float* __restrict__ W_out,
                           const float* __restrict__ b_out,
                           float* __restrict__ out, int G) {
    __shared__ float sp[192];
    int g = blockIdx.x;
    const float* prow = (const float*)g_pooled4 + g * 192;
    if (threadIdx.x < 192) sp[threadIdx.x] = prow[threadIdx.x];
    __syncthreads();
    int c = threadIdx.x;
    if (c < NCLASS) {
        float acc = __ldg(&b_out[c]);
        #pragma unroll 8
        for (int k = 0; k < 192; k++)
            acc = fmaf(sp[k], __ldg(&W_out[k * NCLASS + c]), acc);
        out[g * NCLASS + c] = acc;
    }
}

extern "C" void kernel_launch(void* const* d_in, const int* in_sizes, int n_in,
                              void* d_out, int out_size) {
    const int*   node_ids  = (const int*)  d_in[0];
    const int*   edge_src  = (const int*)  d_in[1];
    const int*   edge_dst  = (const int*)  d_in[2];
    const int*   graph_ids = (const int*)  d_in[3];
    const float* emb       = (const float*)d_in[4];
    const float* Ws        = (const float*)d_in[5];
    const float* bs        = (const float*)d_in[6];
    const float* bn_gamma  = (const float*)d_in[7];
    const float* bn_beta   = (const float*)d_in[8];
    const float* eps       = (const float*)d_in[9];
    const float* W_out     = (const float*)d_in[10];
    const float* b_out     = (const float*)d_in[11];
    float* out = (float*)d_out;

    int N = in_sizes[0];
    int E = in_sizes[1];
    int G = out_size / NCLASS;

    int gN  = (N * 16 + 255) / 256;
    int gE1 = (E + 255) / 256;
    int gZ  = (N + 255) / 256;
    int nb  = (N + SCAN_BS - 1) / SCAN_BS;

    zero_kernel<<<gZ, 256>>>(N);
    hist_kernel<<<gE1, 256>>>(edge_dst, E);
    gather_kernel<<<gN, 256>>>(node_ids, (const float4*)emb, N);
    scanA_kernel<<<nb, SCAN_BS>>>(N);
    scanB_kernel<<<1, MAX_SCAN_BLOCKS>>>(nb);
    scanC_kernel<<<nb, SCAN_BS>>>(N, E);
    fill_kernel<<<gE1, 256>>>(edge_src, edge_dst, E);
    for (int l = 0; l < 3; l++) {
        aggregate_kernel<<<gN, 256>>>(eps, l, N);
        mlp_kernel<<<(N + MLP_BLOCK - 1) / MLP_BLOCK, MLP_BLOCK>>>((const float4*)Ws, bs, l, N);
        stats_kernel<<<512, 256>>>(l, N);
        finalize_kernel<<<gN, 256>>>(graph_ids, bn_gamma, bn_beta, l, N);
    }
    out_kernel<<<G, 192>>>(W_out, b_out, out, G);
}